// round 2
// baseline (speedup 1.0000x reference)
#include <cuda_runtime.h>
#include <cuda_bf16.h>
#include <math.h>

#define NN 100000
#define NE 1000000
#define D  64
#define H  128
#define NG 64
#define CAT 160

// ---------------- scratch (device globals: no runtime alloc) ----------------
__device__ float g_h[NN * D];          // node features
__device__ float g_AB[NN * 2 * H];     // per-node projections: [n][0:128]=h@W1a, [128:256]=h@W1b
__device__ float g_agg[NN * D];        // per-layer aggregation
__device__ float g_dist[NE];
__device__ int   g_kind[NE];
__device__ float g_ktab[2 * H];        // b1 + subunit[kind]@W1c2, per layer
__device__ float g_pool[NG * D];
__device__ float g_cnt[NG];

// ---------------- init: node embedding gather ----------------
__global__ void k_embed(const int* __restrict__ atoms, const float* __restrict__ emb) {
    int i = blockIdx.x * blockDim.x + threadIdx.x;     // over NN*16 float4
    if (i >= NN * (D / 4)) return;
    int n = i >> 4, q = i & 15;
    int a = atoms[n];
    reinterpret_cast<float4*>(g_h)[i] = reinterpret_cast<const float4*>(emb)[a * (D / 4) + q];
}

// ---------------- init: per-edge dist + kind ----------------
__global__ void k_edgeprep(const int* __restrict__ ei, const float* __restrict__ coord,
                           const int* __restrict__ isr) {
    int e = blockIdx.x * blockDim.x + threadIdx.x;
    if (e >= NE) return;
    int s = ei[e], d = ei[NE + e];
    float dx = coord[3 * s + 0] - coord[3 * d + 0];
    float dy = coord[3 * s + 1] - coord[3 * d + 1];
    float dz = coord[3 * s + 2] - coord[3 * d + 2];
    g_dist[e] = sqrtf(dx * dx + dy * dy + dz * dz);
    g_kind[e] = (isr[s] != isr[d]) ? 1 : 0;
}

// ---------------- per layer: kind table = b1 + subunit_embed@W1[144:160] ----------------
__global__ void k_ktab(const float* __restrict__ W1l, const float* __restrict__ b1l,
                       const float* __restrict__ su) {
    int j = threadIdx.x;
    if (j >= H) return;
    for (int kd = 0; kd < 2; kd++) {
        float s = b1l[j];
#pragma unroll
        for (int g = 0; g < 16; g++) s += su[kd * 16 + g] * W1l[(144 + g) * H + j];
        g_ktab[kd * H + j] = s;
    }
}

// ---------------- per layer: AB[n][0:256] = h[n] @ [W1a | W1b] ----------------
__global__ void __launch_bounds__(256) k_nodeproj(const float* __restrict__ W1l) {
    extern __shared__ float sm[];
    float* sW = sm;             // [64][256]
    float* sh = sm + 64 * 256;  // [16][64]
    int t = threadIdx.x;
    int n0 = blockIdx.x * 16;

    for (int idx = t; idx < 64 * 256; idx += 256) {
        int k = idx >> 8, j = idx & 255;
        sW[idx] = (j < H) ? W1l[k * H + j] : W1l[(64 + k) * H + (j - H)];
    }
    for (int idx = t; idx < 16 * 64; idx += 256) {
        int r = idx >> 6, k = idx & 63;
        int n = n0 + r;
        sh[idx] = (n < NN) ? g_h[n * D + k] : 0.f;
    }
    __syncthreads();

    int cg = t & 63;        // 4-col group: cols 4cg..4cg+3 of 256
    int ng = t >> 6;        // 0..3 -> nodes ng, ng+4, ng+8, ng+12
    float4 acc[4];
#pragma unroll
    for (int i = 0; i < 4; i++) acc[i] = make_float4(0.f, 0.f, 0.f, 0.f);

    for (int k = 0; k < 64; k++) {
        float4 w = reinterpret_cast<const float4*>(sW + k * 256)[cg];
#pragma unroll
        for (int i = 0; i < 4; i++) {
            float hv = sh[(ng + 4 * i) * 64 + k];
            acc[i].x += hv * w.x; acc[i].y += hv * w.y;
            acc[i].z += hv * w.z; acc[i].w += hv * w.w;
        }
    }
#pragma unroll
    for (int i = 0; i < 4; i++) {
        int n = n0 + ng + 4 * i;
        if (n < NN) reinterpret_cast<float4*>(g_AB + n * 256)[cg] = acc[i];
    }
}

// ---------------- zero helpers ----------------
__global__ void k_zero_agg() {
    int i = blockIdx.x * blockDim.x + threadIdx.x;
    if (i < NN * (D / 4)) reinterpret_cast<float4*>(g_agg)[i] = make_float4(0.f, 0.f, 0.f, 0.f);
}
__global__ void k_zero_pool() {
    int i = threadIdx.x;
    if (i < NG * (D / 4)) reinterpret_cast<float4*>(g_pool)[i] = make_float4(0.f, 0.f, 0.f, 0.f);
    if (i < NG) g_cnt[i] = 0.f;
}

// ---------------- the big edge kernel ----------------
struct __align__(16) SmemE {
    float yw[64 * 132];     // y (silu output), edge-major, padded rows
    float w2[128 * 64];     // W2 layer slice
    float w1c[16 * 128];    // W1 rows 128..143 (rbf part)
    float rbf[64 * 16];
    float ktab[2 * 128];
    float b2[64];
    float dist[64];
    int   src[64];
    int   dst[64];
    int   kind[64];
};

__global__ void __launch_bounds__(256, 2)
k_edge(const float* __restrict__ W1l, const float* __restrict__ W2l,
       const float* __restrict__ b2l, const int* __restrict__ ei) {
    extern __shared__ char smraw[];
    SmemE* S = reinterpret_cast<SmemE*>(smraw);
    int t = threadIdx.x;
    int e0 = blockIdx.x * 64;

    if (t < 64) {
        int e = e0 + t;
        bool v = (e < NE);
        S->src[t]  = v ? ei[e] : 0;
        S->dst[t]  = v ? ei[NE + e] : 0;
        S->dist[t] = v ? g_dist[e] : 0.f;
        S->kind[t] = v ? g_kind[e] : 0;
        S->b2[t]   = b2l[t];
    }
    for (int idx = t; idx < 128 * 64; idx += 256) S->w2[idx]  = W2l[idx];
    for (int idx = t; idx < 16 * 128; idx += 256) S->w1c[idx] = W1l[128 * H + idx];
    S->ktab[t] = g_ktab[t];   // exactly 256 floats
    __syncthreads();

    // rbf: 64 edges x 16 gaussians; offsets g/3, coeff -4.5
    {
        int e = t >> 2, g0 = (t & 3) * 4;
        float d = S->dist[e];
#pragma unroll
        for (int q = 0; q < 4; q++) {
            float dg = d - (float)(g0 + q) * (1.0f / 3.0f);
            S->rbf[e * 16 + g0 + q] = __expf(-4.5f * dg * dg);
        }
    }
    __syncthreads();

    // ---- stage A: y[e][j] = silu(AB[dst][j] + AB[src][128+j] + ktab[kind][j] + rbf@W1c) ----
    {
        int w = t >> 5, cg = t & 31, c = cg * 4;
        for (int ii = 0; ii < 8; ii++) {
            int e = w * 8 + ii;
            int dn = S->dst[e], sn = S->src[e], kd = S->kind[e];
            float4 a = *reinterpret_cast<const float4*>(g_AB + (size_t)dn * 256 + c);
            float4 b = *reinterpret_cast<const float4*>(g_AB + (size_t)sn * 256 + 128 + c);
            float4 acc = *reinterpret_cast<const float4*>(S->ktab + kd * 128 + c);
            acc.x += a.x + b.x; acc.y += a.y + b.y;
            acc.z += a.z + b.z; acc.w += a.w + b.w;
#pragma unroll
            for (int g = 0; g < 16; g++) {
                float r = S->rbf[e * 16 + g];
                float4 wv = *reinterpret_cast<const float4*>(S->w1c + g * 128 + c);
                acc.x += r * wv.x; acc.y += r * wv.y;
                acc.z += r * wv.z; acc.w += r * wv.w;
            }
            acc.x = __fdividef(acc.x, 1.f + __expf(-acc.x));
            acc.y = __fdividef(acc.y, 1.f + __expf(-acc.y));
            acc.z = __fdividef(acc.z, 1.f + __expf(-acc.z));
            acc.w = __fdividef(acc.w, 1.f + __expf(-acc.w));
            *reinterpret_cast<float4*>(S->yw + e * 132 + c) = acc;
        }
    }
    __syncthreads();

    // ---- stage B: m[e][0:64] = y[e] @ W2 + b2 ; scatter-atomic to g_agg[dst] ----
    {
        int tr = t >> 4, tc = t & 15, c = tc * 4;
        float4 bb = *reinterpret_cast<const float4*>(S->b2 + c);
        float4 acc[4];
#pragma unroll
        for (int i = 0; i < 4; i++) acc[i] = bb;

        const float* y0 = S->yw + (tr * 4 + 0) * 132;
        const float* y1 = S->yw + (tr * 4 + 1) * 132;
        const float* y2 = S->yw + (tr * 4 + 2) * 132;
        const float* y3 = S->yw + (tr * 4 + 3) * 132;

#pragma unroll 4
        for (int k = 0; k < 128; k++) {
            float4 wv = *reinterpret_cast<const float4*>(S->w2 + k * 64 + c);
            float a0 = y0[k], a1 = y1[k], a2 = y2[k], a3 = y3[k];
            acc[0].x += a0 * wv.x; acc[0].y += a0 * wv.y; acc[0].z += a0 * wv.z; acc[0].w += a0 * wv.w;
            acc[1].x += a1 * wv.x; acc[1].y += a1 * wv.y; acc[1].z += a1 * wv.z; acc[1].w += a1 * wv.w;
            acc[2].x += a2 * wv.x; acc[2].y += a2 * wv.y; acc[2].z += a2 * wv.z; acc[2].w += a2 * wv.w;
            acc[3].x += a3 * wv.x; acc[3].y += a3 * wv.y; acc[3].z += a3 * wv.z; acc[3].w += a3 * wv.w;
        }
#pragma unroll
        for (int i = 0; i < 4; i++) {
            int e = tr * 4 + i;
            if (e0 + e < NE) {
                int dn = S->dst[e];
                float* p = g_agg + (size_t)dn * 64 + c;
                atomicAdd(p + 0, acc[i].x);
                atomicAdd(p + 1, acc[i].y);
                atomicAdd(p + 2, acc[i].z);
                atomicAdd(p + 3, acc[i].w);
            }
        }
    }
}

// ---------------- h = relu(h + agg) ----------------
__global__ void k_update() {
    int i = blockIdx.x * blockDim.x + threadIdx.x;
    if (i >= NN * (D / 4)) return;
    float4 h = reinterpret_cast<float4*>(g_h)[i];
    float4 a = reinterpret_cast<float4*>(g_agg)[i];
    h.x = fmaxf(h.x + a.x, 0.f);
    h.y = fmaxf(h.y + a.y, 0.f);
    h.z = fmaxf(h.z + a.z, 0.f);
    h.w = fmaxf(h.w + a.w, 0.f);
    reinterpret_cast<float4*>(g_h)[i] = h;
}

// ---------------- mean pool (batch_ids sorted -> run accumulation) ----------------
__global__ void k_pool(const int* __restrict__ batch) {
    int t = threadIdx.x;
    int c = t & 63, r = t >> 6;
    int n0 = blockIdx.x * 128;
    float s = 0.f, cnt = 0.f;
    int bprev = -1;
    for (int it = 0; it < 32; it++) {
        int n = n0 + r + it * 4;
        if (n < NN) {
            int b = batch[n];
            if (b != bprev) {
                if (bprev >= 0) {
                    atomicAdd(&g_pool[bprev * 64 + c], s);
                    if (c == 0) atomicAdd(&g_cnt[bprev], cnt);
                }
                s = 0.f; cnt = 0.f; bprev = b;
            }
            s += g_h[(size_t)n * 64 + c];
            cnt += 1.f;
        }
    }
    if (bprev >= 0) {
        atomicAdd(&g_pool[bprev * 64 + c], s);
        if (c == 0) atomicAdd(&g_cnt[bprev], cnt);
    }
}

// ---------------- final: out[g] = (pool[g]/cnt) . fc_w + fc_b ----------------
__global__ void k_final(const float* __restrict__ fcw, const float* __restrict__ fcb,
                        float* __restrict__ out) {
    int g = threadIdx.x;
    if (g >= NG) return;
    float cnt = fmaxf(g_cnt[g], 1.f);
    float s = 0.f;
    for (int j = 0; j < 64; j++) s += g_pool[g * 64 + j] * fcw[j];
    out[g] = s / cnt + fcb[0];
}

// ---------------- launch ----------------
extern "C" void kernel_launch(void* const* d_in, const int* in_sizes, int n_in,
                              void* d_out, int out_size) {
    const int*   atoms = (const int*)d_in[0];
    const int*   ei    = (const int*)d_in[1];
    const float* coord = (const float*)d_in[2];
    const int*   isr   = (const int*)d_in[3];
    const int*   batch = (const int*)d_in[4];
    const float* emb   = (const float*)d_in[5];
    const float* su    = (const float*)d_in[6];
    const float* W1    = (const float*)d_in[7];
    const float* b1    = (const float*)d_in[8];
    const float* W2    = (const float*)d_in[9];
    const float* b2    = (const float*)d_in[10];
    const float* fcw   = (const float*)d_in[11];
    const float* fcb   = (const float*)d_in[12];
    float* out = (float*)d_out;

    size_t smP = (size_t)(64 * 256 + 16 * 64) * sizeof(float);
    size_t smE = sizeof(SmemE);
    cudaFuncSetAttribute(k_nodeproj, cudaFuncAttributeMaxDynamicSharedMemorySize, (int)smP);
    cudaFuncSetAttribute(k_edge, cudaFuncAttributeMaxDynamicSharedMemorySize, (int)smE);

    k_embed<<<(NN * 16 + 255) / 256, 256>>>(atoms, emb);
    k_edgeprep<<<(NE + 255) / 256, 256>>>(ei, coord, isr);

    for (int l = 0; l < 4; l++) {
        const float* W1l = W1 + (size_t)l * CAT * H;
        k_ktab<<<1, 128>>>(W1l, b1 + l * H, su);
        k_nodeproj<<<(NN + 15) / 16, 256, smP>>>(W1l);
        k_zero_agg<<<(NN * 16 + 255) / 256, 256>>>();
        k_edge<<<(NE + 63) / 64, 256, smE>>>(W1l, W2 + (size_t)l * H * D, b2 + l * D, ei);
        k_update<<<(NN * 16 + 255) / 256, 256>>>();
    }

    k_zero_pool<<<1, 1024>>>();
    k_pool<<<(NN + 127) / 128, 256>>>(batch);
    k_final<<<1, 64>>>(fcw, fcb, out);
}

// round 4
// speedup vs baseline: 2.4103x; 2.4103x over previous
#include <cuda_runtime.h>
#include <cuda_bf16.h>
#include <math.h>

#define NN 100000
#define NE 1000000
#define D  64
#define H  128
#define NG 64
#define CAT 160

// ---------------- scratch (device globals: no runtime alloc) ----------------
__device__ float g_h[NN * D];              // node features
__device__ float g_AB[(size_t)NN * 2 * H]; // per-node projections [n][0:128]=h@W1a, [128:256]=h@W1b
__device__ float g_aggY[(size_t)NN * H];   // per-node aggregated silu outputs (128-dim)
__device__ float g_deg[NN];                // in-degree (dst counts)
__device__ float g_dist[NE];
__device__ int   g_kind[NE];
__device__ float g_ktab[2 * H];            // b1 + subunit[kind]@W1[144:160]
__device__ float g_pool[NG * D];
__device__ float g_cnt[NG];

__device__ __forceinline__ void red_add_v4(float* p, float4 v) {
    asm volatile("red.global.add.v4.f32 [%0], {%1,%2,%3,%4};"
                 :: "l"(p), "f"(v.x), "f"(v.y), "f"(v.z), "f"(v.w) : "memory");
}

// ---------------- init: node embedding gather ----------------
__global__ void k_embed(const int* __restrict__ atoms, const float* __restrict__ emb) {
    int i = blockIdx.x * blockDim.x + threadIdx.x;     // over NN*16 float4
    if (i >= NN * (D / 4)) return;
    int n = i >> 4, q = i & 15;
    int a = atoms[n];
    reinterpret_cast<float4*>(g_h)[i] = reinterpret_cast<const float4*>(emb)[a * (D / 4) + q];
}

// ---------------- zero degree ----------------
__global__ void k_zero_deg() {
    int i = blockIdx.x * blockDim.x + threadIdx.x;
    if (i < NN) g_deg[i] = 0.f;
}

// ---------------- init: per-edge dist + kind + degree ----------------
__global__ void k_edgeprep(const int* __restrict__ ei, const float* __restrict__ coord,
                           const int* __restrict__ isr) {
    int e = blockIdx.x * blockDim.x + threadIdx.x;
    if (e >= NE) return;
    int s = ei[e], d = ei[NE + e];
    float dx = coord[3 * s + 0] - coord[3 * d + 0];
    float dy = coord[3 * s + 1] - coord[3 * d + 1];
    float dz = coord[3 * s + 2] - coord[3 * d + 2];
    g_dist[e] = sqrtf(dx * dx + dy * dy + dz * dz);
    g_kind[e] = (isr[s] != isr[d]) ? 1 : 0;
    atomicAdd(&g_deg[d], 1.f);
}

// ---------------- per layer: kind table = b1 + subunit_embed@W1[144:160] ----------------
__global__ void k_ktab(const float* __restrict__ W1l, const float* __restrict__ b1l,
                       const float* __restrict__ su) {
    int j = threadIdx.x;
    if (j >= H) return;
    for (int kd = 0; kd < 2; kd++) {
        float s = b1l[j];
#pragma unroll
        for (int g = 0; g < 16; g++) s += su[kd * 16 + g] * W1l[(144 + g) * H + j];
        g_ktab[kd * H + j] = s;
    }
}

// ---------------- per layer: AB[n][0:256] = h[n] @ [W1a | W1b] ----------------
// 32 nodes per block, 8 rows per thread (better FFMA:LDS ratio)
__global__ void __launch_bounds__(256) k_nodeproj(const float* __restrict__ W1l) {
    extern __shared__ float sm[];
    float* sW = sm;             // [64][256]
    float* sh = sm + 64 * 256;  // [32][64]
    int t = threadIdx.x;
    int n0 = blockIdx.x * 32;   // NN = 3125 * 32 exactly

    for (int idx = t; idx < 64 * 256; idx += 256) {
        int k = idx >> 8, j = idx & 255;
        sW[idx] = (j < H) ? W1l[k * H + j] : W1l[(64 + k) * H + (j - H)];
    }
    for (int idx = t; idx < 32 * 64; idx += 256) {
        int r = idx >> 6, k = idx & 63;
        sh[idx] = g_h[(size_t)(n0 + r) * D + k];
    }
    __syncthreads();

    int cg = t & 63;        // 4-col group of 256
    int ng = t >> 6;        // rows ng + 4*i, i<8
    float4 acc[8];
#pragma unroll
    for (int i = 0; i < 8; i++) acc[i] = make_float4(0.f, 0.f, 0.f, 0.f);

#pragma unroll 4
    for (int k = 0; k < 64; k++) {
        float4 w = reinterpret_cast<const float4*>(sW + k * 256)[cg];
#pragma unroll
        for (int i = 0; i < 8; i++) {
            float hv = sh[(ng + 4 * i) * 64 + k];
            acc[i].x += hv * w.x; acc[i].y += hv * w.y;
            acc[i].z += hv * w.z; acc[i].w += hv * w.w;
        }
    }
#pragma unroll
    for (int i = 0; i < 8; i++) {
        int n = n0 + ng + 4 * i;
        reinterpret_cast<float4*>(g_AB + (size_t)n * 256)[cg] = acc[i];
    }
}

// ---------------- zero helpers ----------------
__global__ void k_zeroY() {
    int i = blockIdx.x * blockDim.x + threadIdx.x;
    if (i < NN * (H / 4)) reinterpret_cast<float4*>(g_aggY)[i] = make_float4(0.f, 0.f, 0.f, 0.f);
}
__global__ void k_zero_pool() {
    int i = threadIdx.x;
    if (i < NG * (D / 4)) reinterpret_cast<float4*>(g_pool)[i] = make_float4(0.f, 0.f, 0.f, 0.f);
    if (i < NG) g_cnt[i] = 0.f;
}

// ---------------- edge kernel: one warp per edge ----------------
// y[e][0:128] = silu(AB[dst][0:128] + AB[src][128:256] + ktab[kind] + rbf@W1c)
// red.v4 scatter into g_aggY[dst]
__global__ void __launch_bounds__(256, 2)
k_edge(const int* __restrict__ ei, const float* __restrict__ W1l) {
    int lane = threadIdx.x & 31;
    int warp = threadIdx.x >> 5;
    int e0 = (blockIdx.x * 8 + warp) * 8;   // 8 edges per warp; NE = 15625*64

    // W1c rows 128..143 + ktab, kept in registers
    float4 w1c[16];
#pragma unroll
    for (int g = 0; g < 16; g++)
        w1c[g] = *reinterpret_cast<const float4*>(W1l + (128 + g) * H + 4 * lane);
    float4 kt0 = *reinterpret_cast<const float4*>(g_ktab + 4 * lane);
    float4 kt1 = *reinterpret_cast<const float4*>(g_ktab + 128 + 4 * lane);

    // coalesced edge metadata: 8 distinct addresses per warp
    int m = lane & 7;
    int   sv = ei[e0 + m];
    int   dv = ei[NE + e0 + m];
    float distv = g_dist[e0 + m];
    int   kv = g_kind[e0 + m];

    // prefetch edge 0
    int s = __shfl_sync(0xffffffffu, sv, 0);
    int d = __shfl_sync(0xffffffffu, dv, 0);
    float4 a = *reinterpret_cast<const float4*>(g_AB + (size_t)d * 256 + 4 * lane);
    float4 b = *reinterpret_cast<const float4*>(g_AB + (size_t)s * 256 + 128 + 4 * lane);

#pragma unroll
    for (int i = 0; i < 8; i++) {
        int sn = 0, dn = 0;
        float4 an, bn;
        if (i < 7) {
            sn = __shfl_sync(0xffffffffu, sv, i + 1);
            dn = __shfl_sync(0xffffffffu, dv, i + 1);
            an = *reinterpret_cast<const float4*>(g_AB + (size_t)dn * 256 + 4 * lane);
            bn = *reinterpret_cast<const float4*>(g_AB + (size_t)sn * 256 + 128 + 4 * lane);
        }
        float dist = __shfl_sync(0xffffffffu, distv, i);
        int   kd   = __shfl_sync(0xffffffffu, kv, i);

        // rbf for this edge: lanes 0..15 hold gaussians 0..15
        float dg = dist - (float)(lane & 15) * (1.0f / 3.0f);
        float rbfv = __expf(-4.5f * dg * dg);

        float4 z = kd ? kt1 : kt0;
        z.x += a.x + b.x; z.y += a.y + b.y;
        z.z += a.z + b.z; z.w += a.w + b.w;
#pragma unroll
        for (int g = 0; g < 16; g++) {
            float r = __shfl_sync(0xffffffffu, rbfv, g);
            z.x += r * w1c[g].x; z.y += r * w1c[g].y;
            z.z += r * w1c[g].z; z.w += r * w1c[g].w;
        }
        // silu
        z.x = __fdividef(z.x, 1.f + __expf(-z.x));
        z.y = __fdividef(z.y, 1.f + __expf(-z.y));
        z.z = __fdividef(z.z, 1.f + __expf(-z.z));
        z.w = __fdividef(z.w, 1.f + __expf(-z.w));

        red_add_v4(g_aggY + (size_t)d * 128 + 4 * lane, z);

        s = sn; d = dn; a = an; b = bn;
    }
}

// ---------------- post: h = relu(h + aggY@W2 + deg*b2) ----------------
__global__ void __launch_bounds__(256) k_post(const float* __restrict__ W2l,
                                              const float* __restrict__ b2l) {
    extern __shared__ float sm[];
    float* sW2 = sm;              // [128][64]
    float* sY  = sm + 128 * 64;   // [32][132] padded
    int t = threadIdx.x;
    int n0 = blockIdx.x * 32;     // 3125 blocks

    for (int idx = t; idx < 128 * 64; idx += 256) sW2[idx] = W2l[idx];
    for (int idx = t; idx < 32 * 32; idx += 256) {
        int r = idx >> 5, q = idx & 31;
        *reinterpret_cast<float4*>(sY + r * 132 + 4 * q) =
            *reinterpret_cast<const float4*>(g_aggY + (size_t)(n0 + r) * 128 + 4 * q);
    }
    __syncthreads();

    int tc = t & 15, tr = t >> 4;    // cols 4tc..4tc+3, nodes 2tr, 2tr+1
    int c = tc * 4;
    float4 acc0 = make_float4(0.f, 0.f, 0.f, 0.f);
    float4 acc1 = make_float4(0.f, 0.f, 0.f, 0.f);
    const float* y0 = sY + (2 * tr + 0) * 132;
    const float* y1 = sY + (2 * tr + 1) * 132;

#pragma unroll 4
    for (int k = 0; k < 128; k++) {
        float4 w = *reinterpret_cast<const float4*>(sW2 + k * 64 + c);
        float a0 = y0[k], a1 = y1[k];
        acc0.x += a0 * w.x; acc0.y += a0 * w.y; acc0.z += a0 * w.z; acc0.w += a0 * w.w;
        acc1.x += a1 * w.x; acc1.y += a1 * w.y; acc1.z += a1 * w.z; acc1.w += a1 * w.w;
    }

    float4 bb = *reinterpret_cast<const float4*>(b2l + c);
#pragma unroll
    for (int j = 0; j < 2; j++) {
        int n = n0 + 2 * tr + j;
        float4 acc = j ? acc1 : acc0;
        float dg = g_deg[n];
        float4 hv = *reinterpret_cast<const float4*>(g_h + (size_t)n * 64 + c);
        hv.x = fmaxf(hv.x + acc.x + dg * bb.x, 0.f);
        hv.y = fmaxf(hv.y + acc.y + dg * bb.y, 0.f);
        hv.z = fmaxf(hv.z + acc.z + dg * bb.z, 0.f);
        hv.w = fmaxf(hv.w + acc.w + dg * bb.w, 0.f);
        *reinterpret_cast<float4*>(g_h + (size_t)n * 64 + c) = hv;
    }
}

// ---------------- mean pool (batch_ids sorted -> run accumulation) ----------------
__global__ void k_pool(const int* __restrict__ batch) {
    int t = threadIdx.x;
    int c = t & 63, r = t >> 6;
    int n0 = blockIdx.x * 128;
    float s = 0.f, cnt = 0.f;
    int bprev = -1;
    for (int it = 0; it < 32; it++) {
        int n = n0 + r + it * 4;
        if (n < NN) {
            int b = batch[n];
            if (b != bprev) {
                if (bprev >= 0) {
                    atomicAdd(&g_pool[bprev * 64 + c], s);
                    if (c == 0) atomicAdd(&g_cnt[bprev], cnt);
                }
                s = 0.f; cnt = 0.f; bprev = b;
            }
            s += g_h[(size_t)n * 64 + c];
            cnt += 1.f;
        }
    }
    if (bprev >= 0) {
        atomicAdd(&g_pool[bprev * 64 + c], s);
        if (c == 0) atomicAdd(&g_cnt[bprev], cnt);
    }
}

// ---------------- final: out[g] = (pool[g]/cnt) . fc_w + fc_b ----------------
__global__ void k_final(const float* __restrict__ fcw, const float* __restrict__ fcb,
                        float* __restrict__ out) {
    int g = threadIdx.x;
    if (g >= NG) return;
    float cnt = fmaxf(g_cnt[g], 1.f);
    float s = 0.f;
    for (int j = 0; j < 64; j++) s += g_pool[g * 64 + j] * fcw[j];
    out[g] = s / cnt + fcb[0];
}

// ---------------- launch ----------------
extern "C" void kernel_launch(void* const* d_in, const int* in_sizes, int n_in,
                              void* d_out, int out_size) {
    const int*   atoms = (const int*)d_in[0];
    const int*   ei    = (const int*)d_in[1];
    const float* coord = (const float*)d_in[2];
    const int*   isr   = (const int*)d_in[3];
    const int*   batch = (const int*)d_in[4];
    const float* emb   = (const float*)d_in[5];
    const float* su    = (const float*)d_in[6];
    const float* W1    = (const float*)d_in[7];
    const float* b1    = (const float*)d_in[8];
    const float* W2    = (const float*)d_in[9];
    const float* b2    = (const float*)d_in[10];
    const float* fcw   = (const float*)d_in[11];
    const float* fcb   = (const float*)d_in[12];
    float* out = (float*)d_out;

    size_t smP = (size_t)(64 * 256 + 32 * 64) * sizeof(float);
    size_t smQ = (size_t)(128 * 64 + 32 * 132) * sizeof(float);
    cudaFuncSetAttribute(k_nodeproj, cudaFuncAttributeMaxDynamicSharedMemorySize, (int)smP);
    cudaFuncSetAttribute(k_post, cudaFuncAttributeMaxDynamicSharedMemorySize, (int)smQ);

    k_embed<<<(NN * 16 + 255) / 256, 256>>>(atoms, emb);
    k_zero_deg<<<(NN + 255) / 256, 256>>>();
    k_edgeprep<<<(NE + 255) / 256, 256>>>(ei, coord, isr);

    for (int l = 0; l < 4; l++) {
        const float* W1l = W1 + (size_t)l * CAT * H;
        k_ktab<<<1, 128>>>(W1l, b1 + l * H, su);
        k_nodeproj<<<NN / 32, 256, smP>>>(W1l);
        k_zeroY<<<(NN * 32 + 255) / 256, 256>>>();
        k_edge<<<NE / 64, 256>>>(ei, W1l);
        k_post<<<NN / 32, 256, smQ>>>(W2 + (size_t)l * H * D, b2 + l * D);
    }

    k_zero_pool<<<1, 1024>>>();
    k_pool<<<(NN + 127) / 128, 256>>>(batch);
    k_final<<<1, 64>>>(fcw, fcb, out);
}